// round 15
// baseline (speedup 1.0000x reference)
#include <cuda_runtime.h>
#include <math_constants.h>
#include <cstdint>

#define POOL 7
#define NUM_ROIS 300
#define HH 50
#define WW 50
#define CC 512
#define NPIX (HH * WW)
#define NBINS (POOL * POOL)
#define TOTAL_BINS (NUM_ROIS * NBINS)        // 14700
#define V4_PER_BIN (CC / 4)                  // 128 float4 per bin
#define GRID 300
#define NWARPS (GRID * 8)                    // 2400 warps

// Scratch (no allocation): per-pixel channel max + barrier counters.
__device__ float g_fmax[NPIX];
__device__ unsigned g_bar_in;
__device__ unsigned g_bar_out;

__global__ void __launch_bounds__(256) roi_fused_kernel(
    const float* __restrict__ rois,
    const float* __restrict__ fm,
    float* __restrict__ out) {
    int tid  = threadIdx.x;
    int lane = tid & 31;
    int gw   = blockIdx.x * 8 + (tid >> 5);     // global warp id, 0..2399

    // ---- Phase 1: channel max per pixel (warp per pixel, ~1.04 px/warp) ----
    for (int p = gw; p < NPIX; p += NWARPS) {
        const float4* fp = reinterpret_cast<const float4*>(fm + (size_t)p * CC);
        float m = fmaxf(fmaxf(fp[lane].x, fp[lane].y), fmaxf(fp[lane].z, fp[lane].w));
#pragma unroll
        for (int i = 1; i < 4; i++) {
            float4 v = fp[lane + i * 32];
            m = fmaxf(m, fmaxf(fmaxf(v.x, v.y), fmaxf(v.z, v.w)));
        }
#pragma unroll
        for (int s = 16; s; s >>= 1)
            m = fmaxf(m, __shfl_xor_sync(0xffffffffu, m, s));
        if (lane == 0) g_fmax[p] = m;
    }
    __threadfence();
    __syncthreads();

    // ---- Device-wide barrier (all 300 blocks co-resident) ----
    if (tid == 0) {
        atomicAdd(&g_bar_in, 1u);
        while (atomicAdd(&g_bar_in, 0u) < (unsigned)GRID)
            __nanosleep(32);
    }
    __syncthreads();
    __threadfence();                            // acquire g_fmax from peers

    // ---- Phase 2: warp-per-bin spread streamer (6-7 bins per warp) ----
    const float inv = 1.0f / 16.0f;
    int r = lane >> 3;                          // fixed 8x8 enumeration
    int c = lane & 7;

    for (int g = gw; g < TOTAL_BINS; g += NWARPS) {
        int roi = g / NBINS;                    // const divisors -> mul/shift
        int bin = g - roi * NBINS;
        int bi  = bin / POOL;
        int bj  = bin - bi * POOL;

        int x1 = (int)(rois[roi * 5 + 1] * inv);   // L1-hot after first iter
        int y1 = (int)(rois[roi * 5 + 2] * inv);
        int x2 = (int)(rois[roi * 5 + 3] * inv);
        int y2 = (int)(rois[roi * 5 + 4] * inv);
        int rh = y2 - y1 + 1;
        int rw = x2 - x1 + 1;

        int hs = min(max(y1 + (bi * rh) / POOL, 0), HH);
        int he = min(max(y1 + ((bi + 1) * rh + POOL - 1) / POOL, 0), HH);
        int ws = min(max(x1 + (bj * rw) / POOL, 0), WW);
        int we = min(max(x1 + ((bj + 1) * rw + POOL - 1) / POOL, 0), WW);

        int nh = he - hs;                       // <= 8
        int nw = we - ws;                       // <= 8

        const float* base = g_fmax + hs * WW + ws;
        bool cok = (c < nw);
        float m = -CUDART_INF_F;
        if (cok & (r     < nh)) m = base[r * WW + c];
        if (cok & (r + 4 < nh)) m = fmaxf(m, base[(r + 4) * WW + c]);
#pragma unroll
        for (int s = 16; s; s >>= 1)
            m = fmaxf(m, __shfl_xor_sync(0xffffffffu, m, s));

        float4* o = reinterpret_cast<float4*>(out) + (size_t)g * V4_PER_BIN;
        float4 v4 = make_float4(m, m, m, m);
        __stcs(o + lane,      v4);
        __stcs(o + lane + 32, v4);
        __stcs(o + lane + 64, v4);
        __stcs(o + lane + 96, v4);
    }

    // ---- Barrier counter reset for graph replays (last block out) ----
    if (tid == 0) {
        unsigned t = atomicAdd(&g_bar_out, 1u);
        if (t == (unsigned)(GRID - 1)) {
            atomicExch(&g_bar_in, 0u);
            atomicExch(&g_bar_out, 0u);
        }
    }
}

extern "C" void kernel_launch(void* const* d_in, const int* in_sizes, int n_in,
                              void* d_out, int out_size) {
    const float* rois = (const float*)d_in[0];
    const float* fm   = (const float*)d_in[1];
    if (in_sizes[0] != NUM_ROIS * 5) {
        const float* t = rois; rois = fm; fm = t;
    }
    float* out = (float*)d_out;

    roi_fused_kernel<<<GRID, 256>>>(rois, fm, out);
}

// round 16
// speedup vs baseline: 1.1815x; 1.1815x over previous
#include <cuda_runtime.h>
#include <math_constants.h>
#include <cstdint>

#define POOL 7
#define NUM_ROIS 300
#define HH 50
#define WW 50
#define CC 512
#define NPIX (HH * WW)
#define NBINS (POOL * POOL)
#define TOTAL_BINS (NUM_ROIS * NBINS)        // 14700
#define V4_PER_BIN (CC / 4)                  // 128 float4 per bin
#define WPB 8                                // warps per block (K2)
#define GRID2 1184                           // 148 SMs x 8 blocks: one wave
#define NW2 (GRID2 * WPB)                    // 9472 warps, 1-2 bins each

// Scratch: channel-max per pixel (10 KB). __device__ global (no allocation).
__device__ float g_fmax[NPIX];

// ---------------- K1: channel max per pixel (warp per pixel) ----------------
// 128-thread blocks: 625 blocks spread over more SMs for the exposed window.
__global__ void __launch_bounds__(128) fmax_kernel(const float* __restrict__ fm) {
    int gwarp = (blockIdx.x * blockDim.x + threadIdx.x) >> 5;
    int lane  = threadIdx.x & 31;
    if (gwarp < NPIX) {
        const float4* p = reinterpret_cast<const float4*>(fm + (size_t)gwarp * CC);
        float m = -CUDART_INF_F;
#pragma unroll
        for (int i = 0; i < 4; i++) {
            float4 v = p[lane + i * 32];          // coalesced, MLP=4
            m = fmaxf(m, fmaxf(fmaxf(v.x, v.y), fmaxf(v.z, v.w)));
        }
#pragma unroll
        for (int s = 16; s; s >>= 1)
            m = fmaxf(m, __shfl_xor_sync(0xffffffffu, m, s));
        if (lane == 0) g_fmax[gwarp] = m;
    }
    cudaTriggerProgrammaticLaunchCompletion();
}

// ---------------- K2: persistent single-wave warp-per-bin streamer ---------
// 9472 warps grid-stride 14700 bins (1-2 each). Zero smem, zero barriers:
// butterfly leaves the max in all lanes; 4 streaming STG.128 per lane per bin.
__global__ void __launch_bounds__(WPB * 32) stream_warp_kernel(
    const float* __restrict__ rois, float* __restrict__ out) {
    int tid  = threadIdx.x;
    int lane = tid & 31;
    int gw   = blockIdx.x * WPB + (tid >> 5);   // global warp id
    const float inv = 1.0f / 16.0f;

    // ---- Prologue for the first bin (overlaps K1 tail under PDL) ----
    int g0  = gw;                               // first bin (gw < TOTAL_BINS always)
    int roi = g0 / NBINS;
    int bin = g0 - roi * NBINS;
    int bi  = bin / POOL;
    int bj  = bin - bi * POOL;

    int x1 = (int)(rois[roi * 5 + 1] * inv);
    int y1 = (int)(rois[roi * 5 + 2] * inv);
    int x2 = (int)(rois[roi * 5 + 3] * inv);
    int y2 = (int)(rois[roi * 5 + 4] * inv);
    int rh = y2 - y1 + 1;
    int rw = x2 - x1 + 1;

    int hs = min(max(y1 + (bi * rh) / POOL, 0), HH);
    int he = min(max(y1 + ((bi + 1) * rh + POOL - 1) / POOL, 0), HH);
    int ws = min(max(x1 + (bj * rw) / POOL, 0), WW);
    int we = min(max(x1 + ((bj + 1) * rw + POOL - 1) / POOL, 0), WW);

    cudaGridDependencySynchronize();            // wait for g_fmax

    for (int g = gw; g < TOTAL_BINS; g += NW2) {
        if (g != gw) {                          // recompute window for bin 2
            roi = g / NBINS;
            bin = g - roi * NBINS;
            bi  = bin / POOL;
            bj  = bin - bi * POOL;
            x1 = (int)(rois[roi * 5 + 1] * inv);
            y1 = (int)(rois[roi * 5 + 2] * inv);
            x2 = (int)(rois[roi * 5 + 3] * inv);
            y2 = (int)(rois[roi * 5 + 4] * inv);
            rh = y2 - y1 + 1;
            rw = x2 - x1 + 1;
            hs = min(max(y1 + (bi * rh) / POOL, 0), HH);
            he = min(max(y1 + ((bi + 1) * rh + POOL - 1) / POOL, 0), HH);
            ws = min(max(x1 + (bj * rw) / POOL, 0), WW);
            we = min(max(x1 + ((bj + 1) * rw + POOL - 1) / POOL, 0), WW);
        }

        int nh = he - hs;
        int nw = we - ws;
        int n  = (nh > 0 && nw > 0) ? nh * nw : 0;   // <= 64 cells

        float m = -CUDART_INF_F;
        for (int idx = lane; idx < n; idx += 32) {   // <= 2 iters, L2/L1-hot
            int r = idx / nw;
            int c = idx - r * nw;
            m = fmaxf(m, g_fmax[(hs + r) * WW + (ws + c)]);
        }
#pragma unroll
        for (int s = 16; s; s >>= 1)
            m = fmaxf(m, __shfl_xor_sync(0xffffffffu, m, s));

        float4* o = reinterpret_cast<float4*>(out) + (size_t)g * V4_PER_BIN;
        float4 v4 = make_float4(m, m, m, m);
        __stcs(o + lane,      v4);
        __stcs(o + lane + 32, v4);
        __stcs(o + lane + 64, v4);
        __stcs(o + lane + 96, v4);
    }
}

extern "C" void kernel_launch(void* const* d_in, const int* in_sizes, int n_in,
                              void* d_out, int out_size) {
    const float* rois = (const float*)d_in[0];
    const float* fm   = (const float*)d_in[1];
    if (in_sizes[0] != NUM_ROIS * 5) {
        const float* t = rois; rois = fm; fm = t;
    }
    float* out = (float*)d_out;

    int blocks1 = (NPIX * 32 + 127) / 128;      // 625 blocks x 128 thr
    fmax_kernel<<<blocks1, 128>>>(fm);

    cudaLaunchAttribute attrs[1];
    attrs[0].id = cudaLaunchAttributeProgrammaticStreamSerialization;
    attrs[0].val.programmaticStreamSerializationAllowed = 1;

    cudaLaunchConfig_t cfg = {};
    cfg.gridDim  = dim3(GRID2, 1, 1);
    cfg.blockDim = dim3(WPB * 32, 1, 1);
    cfg.stream   = 0;
    cfg.attrs    = attrs;
    cfg.numAttrs = 1;

    cudaLaunchKernelEx(&cfg, stream_warp_kernel, rois, out);
}